// round 9
// baseline (speedup 1.0000x reference)
#include <cuda_runtime.h>
#include <cuda_bf16.h>
#include <stdint.h>

// ---------------- problem constants ----------------
#define N_NODES 16384
#define NE      524288
#define IN_F    128
#define OUT_F   64
#define N_DOMINO 4160          // sum over rows of ceil((128-ti)/2)
#define N_CTAS   148

// ---------------- device scratch ----------------
__device__ float         g_hw [N_NODES * OUT_F];   // 4 MB
__device__ float         g_agg[N_NODES * OUT_F];   // 4 MB
__device__ __nv_bfloat16 g_xhi[N_NODES * OUT_F];   // 2 MB
__device__ __nv_bfloat16 g_xlo[N_NODES * OUT_F];   // 2 MB
__device__ int           g_is64;

// ---------------- launch 1: fused proj + zero(agg) + detect ----------------
__global__ __launch_bounds__(256) void k_fused1(const float* __restrict__ h,
                                                const float* __restrict__ W,
                                                const unsigned int* __restrict__ srcw) {
    int bid = blockIdx.x;
    int tid = threadIdx.x;
    if (bid < 2048) {
        __shared__ float sW[IN_F * OUT_F];
        __shared__ float sH[8][IN_F];
        int wid = tid >> 5, lid = tid & 31;
        for (int i = tid; i < IN_F * OUT_F; i += 256) sW[i] = W[i];
        int r = bid * 8 + wid;
        #pragma unroll
        for (int t = 0; t < 4; t++) sH[wid][lid + 32 * t] = h[(size_t)r * IN_F + lid + 32 * t];
        __syncthreads();
        float a0 = 0.f, a1 = 0.f;
        #pragma unroll
        for (int k = 0; k < IN_F; k++) {
            float hv = sH[wid][k];
            a0 += hv * sW[k * OUT_F + lid];
            a1 += hv * sW[k * OUT_F + lid + 32];
        }
        g_hw[r * OUT_F + lid]      = a0;
        g_hw[r * OUT_F + lid + 32] = a1;
    } else if (bid < 6144) {
        int i = (bid - 2048) * 256 + tid;
        g_agg[i] = 0.f;
    } else {
        __shared__ int cnt;
        if (tid == 0) cnt = 0;
        __syncthreads();
        int z = 0;
        for (int i = tid; i < 1024; i += 256)
            z += (srcw[2 * i + 1] == 0u) ? 1 : 0;
        atomicAdd(&cnt, z);
        __syncthreads();
        if (tid == 0) g_is64 = (cnt > 512) ? 1 : 0;
    }
}

// ---------------- launch 2: scatter, 2 edges per 16-lane group ----------------
__global__ __launch_bounds__(256) void k2_scatter(const unsigned int* __restrict__ srcw,
                                                  const unsigned int* __restrict__ dstw) {
    unsigned g = (blockIdx.x * 256u + threadIdx.x) >> 4;
    int sub = threadIdx.x & 15;
    unsigned s0, s1, d0, d1;
    if (!g_is64) {
        uint2 sv = *(const uint2*)&srcw[2 * (size_t)g];
        uint2 dv = *(const uint2*)&dstw[2 * (size_t)g];
        s0 = sv.x; s1 = sv.y; d0 = dv.x; d1 = dv.y;
    } else {
        uint4 sv = *(const uint4*)&srcw[4 * (size_t)g];
        uint4 dv = *(const uint4*)&dstw[4 * (size_t)g];
        s0 = sv.x; s1 = sv.z; d0 = dv.x; d1 = dv.z;
    }
    const float4* src = (const float4*)g_hw;
    float4 v0 = src[s0 * 16 + sub];
    asm volatile("red.global.add.v4.f32 [%0], {%1,%2,%3,%4};"
                 :: "l"(&g_agg[d0 * OUT_F + sub * 4]),
                    "f"(v0.x), "f"(v0.y), "f"(v0.z), "f"(v0.w) : "memory");
    float4 v1 = src[s1 * 16 + sub];
    asm volatile("red.global.add.v4.f32 [%0], {%1,%2,%3,%4};"
                 :: "l"(&g_agg[d1 * OUT_F + sub * 4]),
                    "f"(v1.x), "f"(v1.y), "f"(v1.z), "f"(v1.w) : "memory");
}

// ---------------- threefry2x32 (JAX-exact, 20 rounds) ----------------
__device__ __forceinline__ void threefry2x32(uint32_t k0, uint32_t k1,
                                             uint32_t x0, uint32_t x1,
                                             uint32_t& o0, uint32_t& o1) {
    uint32_t ks0 = k0, ks1 = k1, ks2 = 0x1BD11BDAu ^ k0 ^ k1;
    x0 += ks0; x1 += ks1;
#define TF_R(rr) { x0 += x1; x1 = (x1 << (rr)) | (x1 >> (32 - (rr))); x1 ^= x0; }
    TF_R(13) TF_R(15) TF_R(26) TF_R(6)  x0 += ks1; x1 += ks2 + 1u;
    TF_R(17) TF_R(29) TF_R(16) TF_R(24) x0 += ks2; x1 += ks0 + 2u;
    TF_R(13) TF_R(15) TF_R(26) TF_R(6)  x0 += ks0; x1 += ks1 + 3u;
    TF_R(17) TF_R(29) TF_R(16) TF_R(24) x0 += ks1; x1 += ks2 + 4u;
    TF_R(13) TF_R(15) TF_R(26) TF_R(6)  x0 += ks2; x1 += ks0 + 5u;
#undef TF_R
    o0 = x0; o1 = x1;
}

// ---------------- launch 3: relu + dropout mask + bf16 hi/lo split ----------------
__global__ __launch_bounds__(256) void k3_mask(const float* __restrict__ bias) {
    int i = blockIdx.x * 256 + threadIdx.x;
    uint32_t o0, o1;
    threefry2x32(0u, 42u, 0u, (uint32_t)i, o0, o1);
    uint32_t bits = o0 ^ o1;
    float u = __uint_as_float((bits >> 9) | 0x3f800000u) - 1.0f;
    float v = g_agg[i] + bias[i & 63];
    v = fmaxf(v, 0.0f);
    float y = (u < 0.7f) ? (v / 0.7f) : 0.0f;
    __nv_bfloat16 hi = __float2bfloat16(y);
    g_xhi[i] = hi;
    g_xlo[i] = __float2bfloat16(y - __bfloat162float(hi));
}

// ---------------- launch 4: persistent double-buffered symmetric GEMM ----------------
// 148 CTAs x 1024 threads. Work item = "domino" = 128 rows x 256 cols (two adjacent
// upper-triangle 128x128 tiles). Warp grid 4x8 (warp tile 32x32); panel p = wn>>2.
// Buffers: buf[2] of 96KB {Ahi,Alo,B0hi,B0lo,B1hi,B1lo} x 16KB, SW128-swizzled.
// cp.async prefetch of next domino overlaps current mainloop+epilogue; fp32 stage
// reuses the dead current operand buffer.
#define BUF_STRIDE 98304
#define SM_TOTAL   (2 * BUF_STRIDE)   // 192 KB
#define STAGE_STRIDE 136

__device__ __forceinline__ void ldsm_x4(uint32_t* r, uint32_t addr) {
    asm volatile("ldmatrix.sync.aligned.m8n8.x4.shared.b16 {%0,%1,%2,%3}, [%4];"
                 : "=r"(r[0]), "=r"(r[1]), "=r"(r[2]), "=r"(r[3]) : "r"(addr));
}
__device__ __forceinline__ void mma16816(float* d, const uint32_t* a,
                                         uint32_t b0, uint32_t b1) {
    asm volatile(
        "mma.sync.aligned.m16n8k16.row.col.f32.bf16.bf16.f32 "
        "{%0,%1,%2,%3}, {%4,%5,%6,%7}, {%8,%9}, {%0,%1,%2,%3};"
        : "+f"(d[0]), "+f"(d[1]), "+f"(d[2]), "+f"(d[3])
        : "r"(a[0]), "r"(a[1]), "r"(a[2]), "r"(a[3]), "r"(b0), "r"(b1));
}
__device__ __forceinline__ void stg_cs(float* p, float4 v) {
    asm volatile("st.global.cs.v4.f32 [%0], {%1,%2,%3,%4};"
                 :: "l"(p), "f"(v.x), "f"(v.y), "f"(v.z), "f"(v.w) : "memory");
}
__device__ __forceinline__ void cp_async16(uint32_t saddr, const void* gptr) {
    asm volatile("cp.async.cg.shared.global [%0], [%1], 16;"
                 :: "r"(saddr), "l"(gptr) : "memory");
}

__device__ __forceinline__ void decode_work(int w, int& ti, int& tjj) {
    int t = 0, rem = w;
    for (;;) { int cnt = (129 - t) >> 1; if (rem < cnt) break; rem -= cnt; t++; }
    ti = t; tjj = t + 2 * rem;
}

__device__ __forceinline__ void prefetch_domino(uint32_t sbuf, int ti, int tjj, int tid) {
    int rb1 = (tjj + 1 < 128) ? tjj + 1 : 127;   // clamp (stores guarded)
    const __nv_bfloat16* srcs[6] = {
        g_xhi + (size_t)ti  * 128 * OUT_F, g_xlo + (size_t)ti  * 128 * OUT_F,
        g_xhi + (size_t)tjj * 128 * OUT_F, g_xlo + (size_t)tjj * 128 * OUT_F,
        g_xhi + (size_t)rb1 * 128 * OUT_F, g_xlo + (size_t)rb1 * 128 * OUT_F };
    uint32_t bo = (uint32_t)(tid << 4);
    uint32_t sw = bo ^ ((bo >> 3) & 0x70);
    #pragma unroll
    for (int t = 0; t < 6; t++)
        cp_async16(sbuf + t * 16384 + sw, (const char*)srcs[t] + ((size_t)tid << 4));
}

__global__ __launch_bounds__(1024, 1)
void k4_gemm(float* __restrict__ out) {
    extern __shared__ char smem[];
    uint32_t sb = (uint32_t)__cvta_generic_to_shared(smem);
    int tid = threadIdx.x, wid = tid >> 5, lid = tid & 31;
    int wm = wid & 3;            // row group (32 rows)
    int wn = wid >> 2;           // col group (32 cols of 256)
    int p  = wn >> 2;            // panel 0/1
    int wpn = wn & 3;            // col group within panel

    int lrow = lid & 15, lchk = lid >> 4, lswz = lid & 7;
    int gid = lid >> 2, tig = lid & 3;

    int w = blockIdx.x;
    if (w >= N_DOMINO) return;
    int ti, tjj;
    decode_work(w, ti, tjj);
    prefetch_domino(sb, ti, tjj, tid);
    asm volatile("cp.async.commit_group;" ::: "memory");

    int cur = 0;
    while (w < N_DOMINO) {
        // prefetch next domino into other buffer
        int w2 = w + N_CTAS;
        int ti2 = 0, tjj2 = 0;
        if (w2 < N_DOMINO) {
            decode_work(w2, ti2, tjj2);
            prefetch_domino(sb + (cur ^ 1) * BUF_STRIDE, ti2, tjj2, tid);
        }
        asm volatile("cp.async.commit_group;" ::: "memory");
        asm volatile("cp.async.wait_group 1;" ::: "memory");   // current buffer ready
        __syncthreads();

        uint32_t bufb = sb + cur * BUF_STRIDE;
        uint32_t Ahi = bufb, Alo = bufb + 16384;
        uint32_t Bhi = bufb + 32768 + p * 32768, Blo = Bhi + 16384;

        float acc[2][4][4];
        #pragma unroll
        for (int mt = 0; mt < 2; mt++)
            #pragma unroll
            for (int nt = 0; nt < 4; nt++)
                #pragma unroll
                for (int e = 0; e < 4; e++) acc[mt][nt][e] = 0.f;

        #pragma unroll
        for (int kc = 0; kc < 4; kc++) {
            uint32_t chunk = (uint32_t)(((2 * kc + lchk) ^ lswz) << 4);
            uint32_t ah[2][4], al[2][4];
            #pragma unroll
            for (int mt = 0; mt < 2; mt++) {
                uint32_t ro = (uint32_t)((wm * 32 + mt * 16 + lrow) * 128) + chunk;
                ldsm_x4(ah[mt], Ahi + ro);
                ldsm_x4(al[mt], Alo + ro);
            }
            #pragma unroll
            for (int np = 0; np < 2; np++) {
                uint32_t bh[4], bl[4];
                uint32_t ro = (uint32_t)((wpn * 32 + np * 16 + lrow) * 128) + chunk;
                ldsm_x4(bh, Bhi + ro);
                ldsm_x4(bl, Blo + ro);
                #pragma unroll
                for (int mt = 0; mt < 2; mt++)
                    #pragma unroll
                    for (int sel = 0; sel < 2; sel++) {
                        int nt = np * 2 + sel;
                        mma16816(acc[mt][nt], ah[mt], bh[sel], bh[sel + 2]);
                        mma16816(acc[mt][nt], ah[mt], bl[sel], bl[sel + 2]);
                        mma16816(acc[mt][nt], al[mt], bh[sel], bh[sel + 2]);
                    }
            }
        }
        __syncthreads();    // operands in buf[cur] dead -> reuse as stage

        float* stage = (float*)(smem + cur * BUF_STRIDE);

        #pragma unroll
        for (int h = 0; h < 2; h++) {
            int tj = tjj + h;
            bool valid = tj < 128;

            // direct tile (ti, tj): fill by panel-h warps
            if (valid && p == h) {
                #pragma unroll
                for (int mt = 0; mt < 2; mt++)
                    #pragma unroll
                    for (int half = 0; half < 2; half++) {
                        int r = wm * 32 + mt * 16 + gid + 8 * half;
                        #pragma unroll
                        for (int nt = 0; nt < 4; nt++) {
                            int c = wpn * 32 + nt * 8 + tig * 2;
                            *(float2*)&stage[r * STAGE_STRIDE + c] =
                                make_float2(acc[mt][nt][half * 2], acc[mt][nt][half * 2 + 1]);
                        }
                    }
            }
            __syncthreads();
            if (valid) {
                size_t obase = (size_t)(ti * 128) * 16384 + (size_t)tj * 128;
                #pragma unroll
                for (int it = 0; it < 4; it++) {
                    int r = it * 32 + wid;
                    float4 v = *(float4*)&stage[r * STAGE_STRIDE + lid * 4];
                    stg_cs(out + obase + (size_t)r * 16384 + lid * 4, v);
                }
            }
            __syncthreads();

            // transposed tile (tj, ti)
            bool dot = valid && (tj != ti);
            if (dot && p == h) {
                #pragma unroll
                for (int mt = 0; mt < 2; mt++)
                    #pragma unroll
                    for (int half = 0; half < 2; half++) {
                        int r = wm * 32 + mt * 16 + gid + 8 * half;
                        #pragma unroll
                        for (int nt = 0; nt < 4; nt++) {
                            int c = wpn * 32 + nt * 8 + tig * 2;
                            stage[c * STAGE_STRIDE + r]       = acc[mt][nt][half * 2];
                            stage[(c + 1) * STAGE_STRIDE + r] = acc[mt][nt][half * 2 + 1];
                        }
                    }
            }
            __syncthreads();
            if (dot) {
                size_t obase = (size_t)(tj * 128) * 16384 + (size_t)ti * 128;
                #pragma unroll
                for (int it = 0; it < 4; it++) {
                    int r = it * 32 + wid;
                    float4 v = *(float4*)&stage[r * STAGE_STRIDE + lid * 4];
                    stg_cs(out + obase + (size_t)r * 16384 + lid * 4, v);
                }
            }
            __syncthreads();
        }

        w = w2; ti = ti2; tjj = tjj2; cur ^= 1;
    }
}

// ---------------- launch ----------------
extern "C" void kernel_launch(void* const* d_in, const int* in_sizes, int n_in,
                              void* d_out, int out_size) {
    const float*        h    = (const float*)d_in[0];
    const unsigned int* srcw = (const unsigned int*)d_in[1];
    const unsigned int* dstw = (const unsigned int*)d_in[2];
    const float*        W    = (const float*)d_in[3];
    const float*        bias = (const float*)d_in[4];
    float*              out  = (float*)d_out;

    k_fused1<<<6145, 256>>>(h, W, srcw);                    // 1
    k2_scatter<<<(NE / 2 * 16) / 256, 256>>>(srcw, dstw);   // 2
    k3_mask<<<(N_NODES * OUT_F) / 256, 256>>>(bias);        // 3

    cudaFuncSetAttribute(k4_gemm, cudaFuncAttributeMaxDynamicSharedMemorySize, SM_TOTAL);
    k4_gemm<<<N_CTAS, 1024, SM_TOTAL>>>(out);               // 4 (ncu target)
}

// round 10
// speedup vs baseline: 1.0811x; 1.0811x over previous
#include <cuda_runtime.h>
#include <cuda_bf16.h>
#include <stdint.h>

// ---------------- problem constants ----------------
#define N_NODES 16384
#define NE      524288
#define IN_F    128
#define OUT_F   64

// ---------------- device scratch ----------------
__device__ float         g_hw [N_NODES * OUT_F];   // 4 MB
__device__ float         g_agg[N_NODES * OUT_F];   // 4 MB
__device__ __nv_bfloat16 g_xhi[N_NODES * OUT_F];   // 2 MB
__device__ __nv_bfloat16 g_xlo[N_NODES * OUT_F];   // 2 MB
__device__ int           g_is64;

// ---------------- launch 1: fused proj + zero(agg) + detect ----------------
__global__ __launch_bounds__(256) void k_fused1(const float* __restrict__ h,
                                                const float* __restrict__ W,
                                                const unsigned int* __restrict__ srcw) {
    int bid = blockIdx.x;
    int tid = threadIdx.x;
    if (bid < 2048) {
        __shared__ float sW[IN_F * OUT_F];
        __shared__ float sH[8][IN_F];
        int wid = tid >> 5, lid = tid & 31;
        for (int i = tid; i < IN_F * OUT_F; i += 256) sW[i] = W[i];
        int r = bid * 8 + wid;
        #pragma unroll
        for (int t = 0; t < 4; t++) sH[wid][lid + 32 * t] = h[(size_t)r * IN_F + lid + 32 * t];
        __syncthreads();
        float a0 = 0.f, a1 = 0.f;
        #pragma unroll
        for (int k = 0; k < IN_F; k++) {
            float hv = sH[wid][k];
            a0 += hv * sW[k * OUT_F + lid];
            a1 += hv * sW[k * OUT_F + lid + 32];
        }
        g_hw[r * OUT_F + lid]      = a0;
        g_hw[r * OUT_F + lid + 32] = a1;
    } else if (bid < 6144) {
        int i = (bid - 2048) * 256 + tid;
        g_agg[i] = 0.f;
    } else {
        __shared__ int cnt;
        if (tid == 0) cnt = 0;
        __syncthreads();
        int z = 0;
        for (int i = tid; i < 1024; i += 256)
            z += (srcw[2 * i + 1] == 0u) ? 1 : 0;
        atomicAdd(&cnt, z);
        __syncthreads();
        if (tid == 0) g_is64 = (cnt > 512) ? 1 : 0;
    }
}

// ---------------- launch 2: scatter, 2 edges per 16-lane group ----------------
__global__ __launch_bounds__(256) void k2_scatter(const unsigned int* __restrict__ srcw,
                                                  const unsigned int* __restrict__ dstw) {
    unsigned g = (blockIdx.x * 256u + threadIdx.x) >> 4;
    int sub = threadIdx.x & 15;
    unsigned s0, s1, d0, d1;
    if (!g_is64) {
        uint2 sv = *(const uint2*)&srcw[2 * (size_t)g];
        uint2 dv = *(const uint2*)&dstw[2 * (size_t)g];
        s0 = sv.x; s1 = sv.y; d0 = dv.x; d1 = dv.y;
    } else {
        uint4 sv = *(const uint4*)&srcw[4 * (size_t)g];
        uint4 dv = *(const uint4*)&dstw[4 * (size_t)g];
        s0 = sv.x; s1 = sv.z; d0 = dv.x; d1 = dv.z;
    }
    const float4* src = (const float4*)g_hw;
    float4 v0 = src[s0 * 16 + sub];
    asm volatile("red.global.add.v4.f32 [%0], {%1,%2,%3,%4};"
                 :: "l"(&g_agg[d0 * OUT_F + sub * 4]),
                    "f"(v0.x), "f"(v0.y), "f"(v0.z), "f"(v0.w) : "memory");
    float4 v1 = src[s1 * 16 + sub];
    asm volatile("red.global.add.v4.f32 [%0], {%1,%2,%3,%4};"
                 :: "l"(&g_agg[d1 * OUT_F + sub * 4]),
                    "f"(v1.x), "f"(v1.y), "f"(v1.z), "f"(v1.w) : "memory");
}

// ---------------- threefry2x32 (JAX-exact, 20 rounds) ----------------
__device__ __forceinline__ void threefry2x32(uint32_t k0, uint32_t k1,
                                             uint32_t x0, uint32_t x1,
                                             uint32_t& o0, uint32_t& o1) {
    uint32_t ks0 = k0, ks1 = k1, ks2 = 0x1BD11BDAu ^ k0 ^ k1;
    x0 += ks0; x1 += ks1;
#define TF_R(rr) { x0 += x1; x1 = (x1 << (rr)) | (x1 >> (32 - (rr))); x1 ^= x0; }
    TF_R(13) TF_R(15) TF_R(26) TF_R(6)  x0 += ks1; x1 += ks2 + 1u;
    TF_R(17) TF_R(29) TF_R(16) TF_R(24) x0 += ks2; x1 += ks0 + 2u;
    TF_R(13) TF_R(15) TF_R(26) TF_R(6)  x0 += ks0; x1 += ks1 + 3u;
    TF_R(17) TF_R(29) TF_R(16) TF_R(24) x0 += ks1; x1 += ks2 + 4u;
    TF_R(13) TF_R(15) TF_R(26) TF_R(6)  x0 += ks2; x1 += ks0 + 5u;
#undef TF_R
    o0 = x0; o1 = x1;
}

// ---------------- launch 3: relu + dropout mask + bf16 hi/lo split ----------------
__global__ __launch_bounds__(256) void k3_mask(const float* __restrict__ bias) {
    int i = blockIdx.x * 256 + threadIdx.x;
    uint32_t o0, o1;
    threefry2x32(0u, 42u, 0u, (uint32_t)i, o0, o1);
    uint32_t bits = o0 ^ o1;
    float u = __uint_as_float((bits >> 9) | 0x3f800000u) - 1.0f;
    float v = g_agg[i] + bias[i & 63];
    v = fmaxf(v, 0.0f);
    float y = (u < 0.7f) ? (v / 0.7f) : 0.0f;
    __nv_bfloat16 hi = __float2bfloat16(y);
    g_xhi[i] = hi;
    g_xlo[i] = __float2bfloat16(y - __bfloat162float(hi));
}

// ---------------- launch 4: out = x @ x^T, full grid of 128x64 tiles ----------------
// 32768 CTAs x 256 threads, 4 CTAs/SM (48KB smem each). Warp grid 4x2 (32x32 tiles).
// Short CTA chain: cp.async load -> mainloop -> single stage -> single store pass.
// Many small independent CTAs keep the DRAM store stream continuously fed.
#define SM_AHI  0
#define SM_ALO  16384
#define SM_BHI  32768
#define SM_BLO  40960
#define SM_TOTAL 49152
#define STAGE_STRIDE 72   // floats; stage = 128 x 72 x 4B = 36864 B (reuses operand smem)

__device__ __forceinline__ void ldsm_x4(uint32_t* r, uint32_t addr) {
    asm volatile("ldmatrix.sync.aligned.m8n8.x4.shared.b16 {%0,%1,%2,%3}, [%4];"
                 : "=r"(r[0]), "=r"(r[1]), "=r"(r[2]), "=r"(r[3]) : "r"(addr));
}
__device__ __forceinline__ void mma16816(float* d, const uint32_t* a,
                                         uint32_t b0, uint32_t b1) {
    asm volatile(
        "mma.sync.aligned.m16n8k16.row.col.f32.bf16.bf16.f32 "
        "{%0,%1,%2,%3}, {%4,%5,%6,%7}, {%8,%9}, {%0,%1,%2,%3};"
        : "+f"(d[0]), "+f"(d[1]), "+f"(d[2]), "+f"(d[3])
        : "r"(a[0]), "r"(a[1]), "r"(a[2]), "r"(a[3]), "r"(b0), "r"(b1));
}
__device__ __forceinline__ void stg_cs(float* p, float4 v) {
    asm volatile("st.global.cs.v4.f32 [%0], {%1,%2,%3,%4};"
                 :: "l"(p), "f"(v.x), "f"(v.y), "f"(v.z), "f"(v.w) : "memory");
}
__device__ __forceinline__ void cp_async16(uint32_t saddr, const void* gptr) {
    asm volatile("cp.async.cg.shared.global [%0], [%1], 16;"
                 :: "r"(saddr), "l"(gptr) : "memory");
}

__global__ __launch_bounds__(256, 4)
void k4_gemm(float* __restrict__ out) {
    extern __shared__ char smem[];
    uint32_t sb = (uint32_t)__cvta_generic_to_shared(smem);
    int tid = threadIdx.x, wid = tid >> 5, lid = tid & 31;
    int wm = wid & 3, wn = wid >> 2;   // 4x2 warp grid; warp tile 32 rows x 32 cols

    int bid = blockIdx.x;
    int rowA = (bid & 127) << 7;       // 128-row block
    int colB = (bid >> 7) << 6;        // 64-col block

    // ---- prologue: cp.async operand tiles with SW128 swizzle ----
    {
        // A: 128 rows x 128B (hi, lo) = 1024 chunks each; B: 64 rows = 512 chunks each
        const char* pAh = (const char*)(g_xhi + (size_t)rowA * OUT_F);
        const char* pAl = (const char*)(g_xlo + (size_t)rowA * OUT_F);
        const char* pBh = (const char*)(g_xhi + (size_t)colB * OUT_F);
        const char* pBl = (const char*)(g_xlo + (size_t)colB * OUT_F);
        #pragma unroll
        for (int j = 0; j < 4; j++) {
            int idx = tid + j * 256;
            uint32_t bo = (uint32_t)(idx << 4);
            uint32_t sw = bo ^ ((bo >> 3) & 0x70);
            cp_async16(sb + SM_AHI + sw, pAh + ((size_t)idx << 4));
            cp_async16(sb + SM_ALO + sw, pAl + ((size_t)idx << 4));
        }
        #pragma unroll
        for (int j = 0; j < 2; j++) {
            int idx = tid + j * 256;
            uint32_t bo = (uint32_t)(idx << 4);
            uint32_t sw = bo ^ ((bo >> 3) & 0x70);
            cp_async16(sb + SM_BHI + sw, pBh + ((size_t)idx << 4));
            cp_async16(sb + SM_BLO + sw, pBl + ((size_t)idx << 4));
        }
        asm volatile("cp.async.commit_group;" ::: "memory");
        asm volatile("cp.async.wait_group 0;" ::: "memory");
    }
    __syncthreads();

    float acc[2][4][4];
    #pragma unroll
    for (int mt = 0; mt < 2; mt++)
        #pragma unroll
        for (int nt = 0; nt < 4; nt++)
            #pragma unroll
            for (int e = 0; e < 4; e++) acc[mt][nt][e] = 0.f;

    int lrow = lid & 15, lchk = lid >> 4, lswz = lid & 7;

    #pragma unroll
    for (int kc = 0; kc < 4; kc++) {
        uint32_t chunk = (uint32_t)(((2 * kc + lchk) ^ lswz) << 4);
        uint32_t ah[2][4], al[2][4];
        #pragma unroll
        for (int mt = 0; mt < 2; mt++) {
            uint32_t ro = (uint32_t)((wm * 32 + mt * 16 + lrow) * 128) + chunk;
            ldsm_x4(ah[mt], sb + SM_AHI + ro);
            ldsm_x4(al[mt], sb + SM_ALO + ro);
        }
        #pragma unroll
        for (int np = 0; np < 2; np++) {
            uint32_t bh[4], bl[4];
            uint32_t ro = (uint32_t)((wn * 32 + np * 16 + lrow) * 128) + chunk;
            ldsm_x4(bh, sb + SM_BHI + ro);
            ldsm_x4(bl, sb + SM_BLO + ro);
            #pragma unroll
            for (int mt = 0; mt < 2; mt++)
                #pragma unroll
                for (int sel = 0; sel < 2; sel++) {
                    int nt = np * 2 + sel;
                    mma16816(acc[mt][nt], ah[mt], bh[sel], bh[sel + 2]); // hi*hi
                    mma16816(acc[mt][nt], ah[mt], bl[sel], bl[sel + 2]); // hi*lo
                    mma16816(acc[mt][nt], al[mt], bh[sel], bh[sel + 2]); // lo*hi
                }
        }
    }
    __syncthreads();   // operands dead; reuse smem as fp32 stage

    float* stage = (float*)smem;    // [128][STAGE_STRIDE]
    int gid = lid >> 2, tig = lid & 3;

    #pragma unroll
    for (int mt = 0; mt < 2; mt++)
        #pragma unroll
        for (int half = 0; half < 2; half++) {
            int r = wm * 32 + mt * 16 + gid + 8 * half;
            #pragma unroll
            for (int nt = 0; nt < 4; nt++) {
                int c = wn * 32 + nt * 8 + tig * 2;
                *(float2*)&stage[r * STAGE_STRIDE + c] =
                    make_float2(acc[mt][nt][half * 2], acc[mt][nt][half * 2 + 1]);
            }
        }
    __syncthreads();

    // coalesced stores: each warp covers 2 rows/iter (row segment = 64 floats = 256B)
    {
        size_t obase = (size_t)rowA * 16384 + colB;
        int rsub = lid >> 4;            // 0/1: which of the 2 rows
        int csub = (lid & 15) * 4;      // float4 column within 64
        #pragma unroll
        for (int it = 0; it < 8; it++) {
            int r = it * 16 + wid * 2 + rsub;
            float4 v = *(float4*)&stage[r * STAGE_STRIDE + csub];
            stg_cs(out + obase + (size_t)r * 16384 + csub, v);
        }
    }
}

// ---------------- launch ----------------
extern "C" void kernel_launch(void* const* d_in, const int* in_sizes, int n_in,
                              void* d_out, int out_size) {
    const float*        h    = (const float*)d_in[0];
    const unsigned int* srcw = (const unsigned int*)d_in[1];
    const unsigned int* dstw = (const unsigned int*)d_in[2];
    const float*        W    = (const float*)d_in[3];
    const float*        bias = (const float*)d_in[4];
    float*              out  = (float*)d_out;

    k_fused1<<<6145, 256>>>(h, W, srcw);                    // 1
    k2_scatter<<<(NE / 2 * 16) / 256, 256>>>(srcw, dstw);   // 2
    k3_mask<<<(N_NODES * OUT_F) / 256, 256>>>(bias);        // 3

    cudaFuncSetAttribute(k4_gemm, cudaFuncAttributeMaxDynamicSharedMemorySize, SM_TOTAL);
    k4_gemm<<<128 * 256, 256, SM_TOTAL>>>(out);             // 4 (ncu target)
}

// round 11
// speedup vs baseline: 1.3087x; 1.2105x over previous
#include <cuda_runtime.h>
#include <cuda_bf16.h>
#include <stdint.h>

// ---------------- problem constants ----------------
#define N_NODES 16384
#define NE      524288
#define IN_F    128
#define OUT_F   64

// ---------------- device scratch ----------------
__device__ float         g_hw [N_NODES * OUT_F];   // 4 MB
__device__ float         g_agg[N_NODES * OUT_F];   // 4 MB
__device__ __nv_bfloat16 g_xhi[N_NODES * OUT_F];   // 2 MB
__device__ __nv_bfloat16 g_xlo[N_NODES * OUT_F];   // 2 MB
__device__ int           g_is64;

// ---------------- launch 1: fused proj + zero(agg) + detect ----------------
__global__ __launch_bounds__(256) void k_fused1(const float* __restrict__ h,
                                                const float* __restrict__ W,
                                                const unsigned int* __restrict__ srcw) {
    int bid = blockIdx.x;
    int tid = threadIdx.x;
    if (bid < 2048) {
        __shared__ float sW[IN_F * OUT_F];
        __shared__ float sH[8][IN_F];
        int wid = tid >> 5, lid = tid & 31;
        for (int i = tid; i < IN_F * OUT_F; i += 256) sW[i] = W[i];
        int r = bid * 8 + wid;
        #pragma unroll
        for (int t = 0; t < 4; t++) sH[wid][lid + 32 * t] = h[(size_t)r * IN_F + lid + 32 * t];
        __syncthreads();
        float a0 = 0.f, a1 = 0.f;
        #pragma unroll
        for (int k = 0; k < IN_F; k++) {
            float hv = sH[wid][k];
            a0 += hv * sW[k * OUT_F + lid];
            a1 += hv * sW[k * OUT_F + lid + 32];
        }
        g_hw[r * OUT_F + lid]      = a0;
        g_hw[r * OUT_F + lid + 32] = a1;
    } else if (bid < 6144) {
        int i = (bid - 2048) * 256 + tid;
        g_agg[i] = 0.f;
    } else {
        __shared__ int cnt;
        if (tid == 0) cnt = 0;
        __syncthreads();
        int z = 0;
        for (int i = tid; i < 1024; i += 256)
            z += (srcw[2 * i + 1] == 0u) ? 1 : 0;
        atomicAdd(&cnt, z);
        __syncthreads();
        if (tid == 0) g_is64 = (cnt > 512) ? 1 : 0;
    }
}

// ---------------- launch 2: scatter, 2 edges per 16-lane group ----------------
__global__ __launch_bounds__(256) void k2_scatter(const unsigned int* __restrict__ srcw,
                                                  const unsigned int* __restrict__ dstw) {
    unsigned g = (blockIdx.x * 256u + threadIdx.x) >> 4;
    int sub = threadIdx.x & 15;
    unsigned s0, s1, d0, d1;
    if (!g_is64) {
        uint2 sv = *(const uint2*)&srcw[2 * (size_t)g];
        uint2 dv = *(const uint2*)&dstw[2 * (size_t)g];
        s0 = sv.x; s1 = sv.y; d0 = dv.x; d1 = dv.y;
    } else {
        uint4 sv = *(const uint4*)&srcw[4 * (size_t)g];
        uint4 dv = *(const uint4*)&dstw[4 * (size_t)g];
        s0 = sv.x; s1 = sv.z; d0 = dv.x; d1 = dv.z;
    }
    const float4* src = (const float4*)g_hw;
    float4 v0 = src[s0 * 16 + sub];
    asm volatile("red.global.add.v4.f32 [%0], {%1,%2,%3,%4};"
                 :: "l"(&g_agg[d0 * OUT_F + sub * 4]),
                    "f"(v0.x), "f"(v0.y), "f"(v0.z), "f"(v0.w) : "memory");
    float4 v1 = src[s1 * 16 + sub];
    asm volatile("red.global.add.v4.f32 [%0], {%1,%2,%3,%4};"
                 :: "l"(&g_agg[d1 * OUT_F + sub * 4]),
                    "f"(v1.x), "f"(v1.y), "f"(v1.z), "f"(v1.w) : "memory");
}

// ---------------- threefry2x32 (JAX-exact, 20 rounds) ----------------
__device__ __forceinline__ void threefry2x32(uint32_t k0, uint32_t k1,
                                             uint32_t x0, uint32_t x1,
                                             uint32_t& o0, uint32_t& o1) {
    uint32_t ks0 = k0, ks1 = k1, ks2 = 0x1BD11BDAu ^ k0 ^ k1;
    x0 += ks0; x1 += ks1;
#define TF_R(rr) { x0 += x1; x1 = (x1 << (rr)) | (x1 >> (32 - (rr))); x1 ^= x0; }
    TF_R(13) TF_R(15) TF_R(26) TF_R(6)  x0 += ks1; x1 += ks2 + 1u;
    TF_R(17) TF_R(29) TF_R(16) TF_R(24) x0 += ks2; x1 += ks0 + 2u;
    TF_R(13) TF_R(15) TF_R(26) TF_R(6)  x0 += ks0; x1 += ks1 + 3u;
    TF_R(17) TF_R(29) TF_R(16) TF_R(24) x0 += ks1; x1 += ks2 + 4u;
    TF_R(13) TF_R(15) TF_R(26) TF_R(6)  x0 += ks2; x1 += ks0 + 5u;
#undef TF_R
    o0 = x0; o1 = x1;
}

// ---------------- launch 3: relu + dropout mask + bf16 hi/lo split ----------------
__global__ __launch_bounds__(256) void k3_mask(const float* __restrict__ bias) {
    int i = blockIdx.x * 256 + threadIdx.x;
    uint32_t o0, o1;
    threefry2x32(0u, 42u, 0u, (uint32_t)i, o0, o1);
    uint32_t bits = o0 ^ o1;
    float u = __uint_as_float((bits >> 9) | 0x3f800000u) - 1.0f;
    float v = g_agg[i] + bias[i & 63];
    v = fmaxf(v, 0.0f);
    float y = (u < 0.7f) ? (v / 0.7f) : 0.0f;
    __nv_bfloat16 hi = __float2bfloat16(y);
    g_xhi[i] = hi;
    g_xlo[i] = __float2bfloat16(y - __bfloat162float(hi));
}

// ---------------- launch 4: out = x @ x^T, triangular, async bulk stores ----------------
// R7 champion structure (512 thr, 4x4 warp grid, 2 CTA/SM) with the epilogue's
// warp-synchronous STGs replaced by cp.async.bulk S2G (TMA-path, fire-and-forget).
#define SM_AHI  0
#define SM_ALO  16384
#define SM_BHI  32768
#define SM_BLO  49152
#define STAGE_STRIDE 136                  // floats; 544 B row pitch (16B aligned)
#define SM_TOTAL (128 * STAGE_STRIDE * 4) // 69632 B

__device__ __forceinline__ void ldsm_x4(uint32_t* r, uint32_t addr) {
    asm volatile("ldmatrix.sync.aligned.m8n8.x4.shared.b16 {%0,%1,%2,%3}, [%4];"
                 : "=r"(r[0]), "=r"(r[1]), "=r"(r[2]), "=r"(r[3]) : "r"(addr));
}
__device__ __forceinline__ void mma16816(float* d, const uint32_t* a,
                                         uint32_t b0, uint32_t b1) {
    asm volatile(
        "mma.sync.aligned.m16n8k16.row.col.f32.bf16.bf16.f32 "
        "{%0,%1,%2,%3}, {%4,%5,%6,%7}, {%8,%9}, {%0,%1,%2,%3};"
        : "+f"(d[0]), "+f"(d[1]), "+f"(d[2]), "+f"(d[3])
        : "r"(a[0]), "r"(a[1]), "r"(a[2]), "r"(a[3]), "r"(b0), "r"(b1));
}
__device__ __forceinline__ void cp_async16(uint32_t saddr, const void* gptr) {
    asm volatile("cp.async.cg.shared.global [%0], [%1], 16;"
                 :: "r"(saddr), "l"(gptr) : "memory");
}
__device__ __forceinline__ void bulk_store_row(void* gptr, uint32_t saddr) {
    asm volatile("cp.async.bulk.global.shared::cta.bulk_group [%0], [%1], %2;"
                 :: "l"(gptr), "r"(saddr), "r"(512u) : "memory");
}

__global__ __launch_bounds__(512, 2)
void k4_gemm(float* __restrict__ out) {
    extern __shared__ char smem[];
    uint32_t sb = (uint32_t)__cvta_generic_to_shared(smem);
    int tid = threadIdx.x, wid = tid >> 5, lid = tid & 31;
    int wm = wid & 3, wn = wid >> 2;   // 4x4 warp grid, warp tile 32x32

    int bid = blockIdx.x;
    int ti = (int)((257.0 - sqrt(66049.0 - 8.0 * (double)bid)) * 0.5);
    while ((ti + 1) * 128 - ((ti + 1) * ti) / 2 <= bid) ti++;
    while (ti * 128 - (ti * (ti - 1)) / 2 > bid) ti--;
    int tj = ti + (bid - (ti * 128 - (ti * (ti - 1)) / 2));
    int rowA = ti << 7;
    int rowB = tj << 7;

    // ---- prologue: cp.async operand tiles with SW128 swizzle ----
    {
        const __nv_bfloat16* bases[4] = {
            g_xhi + (size_t)rowA * OUT_F, g_xlo + (size_t)rowA * OUT_F,
            g_xhi + (size_t)rowB * OUT_F, g_xlo + (size_t)rowB * OUT_F };
        const int offs[4] = { SM_AHI, SM_ALO, SM_BHI, SM_BLO };
        #pragma unroll
        for (int t = 0; t < 4; t++) {
            const char* gp = (const char*)bases[t];
            #pragma unroll
            for (int j = 0; j < 2; j++) {
                int idx = tid + j * 512;
                uint32_t bo = (uint32_t)(idx << 4);
                uint32_t sw = bo ^ ((bo >> 3) & 0x70);
                cp_async16(sb + offs[t] + sw, gp + ((size_t)idx << 4));
            }
        }
        asm volatile("cp.async.commit_group;" ::: "memory");
        asm volatile("cp.async.wait_group 0;" ::: "memory");
    }
    __syncthreads();

    float acc[2][4][4];
    #pragma unroll
    for (int mt = 0; mt < 2; mt++)
        #pragma unroll
        for (int nt = 0; nt < 4; nt++)
            #pragma unroll
            for (int e = 0; e < 4; e++) acc[mt][nt][e] = 0.f;

    int lrow = lid & 15, lchk = lid >> 4, lswz = lid & 7;

    #pragma unroll
    for (int kc = 0; kc < 4; kc++) {
        uint32_t chunk = (uint32_t)(((2 * kc + lchk) ^ lswz) << 4);
        uint32_t ah[2][4], al[2][4];
        #pragma unroll
        for (int mt = 0; mt < 2; mt++) {
            uint32_t ro = (uint32_t)((wm * 32 + mt * 16 + lrow) * 128) + chunk;
            ldsm_x4(ah[mt], sb + SM_AHI + ro);
            ldsm_x4(al[mt], sb + SM_ALO + ro);
        }
        #pragma unroll
        for (int np = 0; np < 2; np++) {
            uint32_t bh[4], bl[4];
            uint32_t ro = (uint32_t)((wn * 32 + np * 16 + lrow) * 128) + chunk;
            ldsm_x4(bh, sb + SM_BHI + ro);
            ldsm_x4(bl, sb + SM_BLO + ro);
            #pragma unroll
            for (int mt = 0; mt < 2; mt++)
                #pragma unroll
                for (int sel = 0; sel < 2; sel++) {
                    int nt = np * 2 + sel;
                    mma16816(acc[mt][nt], ah[mt], bh[sel], bh[sel + 2]); // hi*hi
                    mma16816(acc[mt][nt], ah[mt], bl[sel], bl[sel + 2]); // hi*lo
                    mma16816(acc[mt][nt], al[mt], bh[sel], bh[sel + 2]); // lo*hi
                }
        }
    }
    __syncthreads();   // operands dead; reuse smem as fp32 stage

    float* stage = (float*)smem;    // [128][STAGE_STRIDE]
    int gid = lid >> 2, tig = lid & 3;

    // ---- pass 1: direct tile -> stage -> async bulk stores ----
    #pragma unroll
    for (int mt = 0; mt < 2; mt++)
        #pragma unroll
        for (int half = 0; half < 2; half++) {
            int r = wm * 32 + mt * 16 + gid + 8 * half;
            #pragma unroll
            for (int nt = 0; nt < 4; nt++) {
                int c = wn * 32 + nt * 8 + tig * 2;
                *(float2*)&stage[r * STAGE_STRIDE + c] =
                    make_float2(acc[mt][nt][half * 2], acc[mt][nt][half * 2 + 1]);
            }
        }
    __syncthreads();
    if (tid < 128) {
        asm volatile("fence.proxy.async.shared::cta;" ::: "memory");
        size_t obase = (size_t)rowA * 16384 + rowB;
        bulk_store_row(out + obase + (size_t)tid * 16384,
                       sb + (uint32_t)(tid * STAGE_STRIDE * 4));
        asm volatile("cp.async.bulk.commit_group;" ::: "memory");
    }

    // ---- pass 2: transposed tile (skip on diagonal) ----
    if (ti != tj) {
        if (tid < 128)
            asm volatile("cp.async.bulk.wait_group 0;" ::: "memory");  // stage reusable
        __syncthreads();
        #pragma unroll
        for (int mt = 0; mt < 2; mt++)
            #pragma unroll
            for (int half = 0; half < 2; half++) {
                int r = wm * 32 + mt * 16 + gid + 8 * half;
                #pragma unroll
                for (int nt = 0; nt < 4; nt++) {
                    int c = wn * 32 + nt * 8 + tig * 2;
                    stage[c * STAGE_STRIDE + r]       = acc[mt][nt][half * 2];
                    stage[(c + 1) * STAGE_STRIDE + r] = acc[mt][nt][half * 2 + 1];
                }
            }
        __syncthreads();
        if (tid < 128) {
            asm volatile("fence.proxy.async.shared::cta;" ::: "memory");
            size_t obase = (size_t)rowB * 16384 + rowA;
            bulk_store_row(out + obase + (size_t)tid * 16384,
                           sb + (uint32_t)(tid * STAGE_STRIDE * 4));
            asm volatile("cp.async.bulk.commit_group;" ::: "memory");
        }
    }

    // drain before CTA exit (smem dealloc safety + write visibility)
    if (tid < 128)
        asm volatile("cp.async.bulk.wait_group 0;" ::: "memory");
}

// ---------------- launch ----------------
extern "C" void kernel_launch(void* const* d_in, const int* in_sizes, int n_in,
                              void* d_out, int out_size) {
    const float*        h    = (const float*)d_in[0];
    const unsigned int* srcw = (const unsigned int*)d_in[1];
    const unsigned int* dstw = (const unsigned int*)d_in[2];
    const float*        W    = (const float*)d_in[3];
    const float*        bias = (const float*)d_in[4];
    float*              out  = (float*)d_out;

    k_fused1<<<6145, 256>>>(h, W, srcw);                    // 1
    k2_scatter<<<(NE / 2 * 16) / 256, 256>>>(srcw, dstw);   // 2
    k3_mask<<<(N_NODES * OUT_F) / 256, 256>>>(bias);        // 3

    cudaFuncSetAttribute(k4_gemm, cudaFuncAttributeMaxDynamicSharedMemorySize, SM_TOTAL);
    k4_gemm<<<(128 * 129) / 2, 512, SM_TOTAL>>>(out);       // 4 (ncu target)
}

// round 12
// speedup vs baseline: 1.4809x; 1.1316x over previous
#include <cuda_runtime.h>
#include <cuda_bf16.h>
#include <stdint.h>

// ---------------- problem constants ----------------
#define N_NODES 16384
#define NE      524288
#define IN_F    128
#define OUT_F   64
#define N_TILES 16512   // sum over ti of (256 - 2*ti)

// ---------------- device scratch ----------------
__device__ float         g_hw [N_NODES * OUT_F];   // 4 MB
__device__ float         g_agg[N_NODES * OUT_F];   // 4 MB
__device__ __nv_bfloat16 g_xhi[N_NODES * OUT_F];   // 2 MB
__device__ __nv_bfloat16 g_xlo[N_NODES * OUT_F];   // 2 MB
__device__ int           g_is64;

// ---------------- launch 1: fused proj + zero(agg) + detect ----------------
__global__ __launch_bounds__(256) void k_fused1(const float* __restrict__ h,
                                                const float* __restrict__ W,
                                                const unsigned int* __restrict__ srcw) {
    int bid = blockIdx.x;
    int tid = threadIdx.x;
    if (bid < 2048) {
        __shared__ float sW[IN_F * OUT_F];
        __shared__ float sH[8][IN_F];
        int wid = tid >> 5, lid = tid & 31;
        for (int i = tid; i < IN_F * OUT_F; i += 256) sW[i] = W[i];
        int r = bid * 8 + wid;
        #pragma unroll
        for (int t = 0; t < 4; t++) sH[wid][lid + 32 * t] = h[(size_t)r * IN_F + lid + 32 * t];
        __syncthreads();
        float a0 = 0.f, a1 = 0.f;
        #pragma unroll
        for (int k = 0; k < IN_F; k++) {
            float hv = sH[wid][k];
            a0 += hv * sW[k * OUT_F + lid];
            a1 += hv * sW[k * OUT_F + lid + 32];
        }
        g_hw[r * OUT_F + lid]      = a0;
        g_hw[r * OUT_F + lid + 32] = a1;
    } else if (bid < 6144) {
        int i = (bid - 2048) * 256 + tid;
        g_agg[i] = 0.f;
    } else {
        __shared__ int cnt;
        if (tid == 0) cnt = 0;
        __syncthreads();
        int z = 0;
        for (int i = tid; i < 1024; i += 256)
            z += (srcw[2 * i + 1] == 0u) ? 1 : 0;
        atomicAdd(&cnt, z);
        __syncthreads();
        if (tid == 0) g_is64 = (cnt > 512) ? 1 : 0;
    }
}

// ---------------- launch 2: scatter, 2 edges per 16-lane group ----------------
__global__ __launch_bounds__(256) void k2_scatter(const unsigned int* __restrict__ srcw,
                                                  const unsigned int* __restrict__ dstw) {
    unsigned g = (blockIdx.x * 256u + threadIdx.x) >> 4;
    int sub = threadIdx.x & 15;
    unsigned s0, s1, d0, d1;
    if (!g_is64) {
        uint2 sv = *(const uint2*)&srcw[2 * (size_t)g];
        uint2 dv = *(const uint2*)&dstw[2 * (size_t)g];
        s0 = sv.x; s1 = sv.y; d0 = dv.x; d1 = dv.y;
    } else {
        uint4 sv = *(const uint4*)&srcw[4 * (size_t)g];
        uint4 dv = *(const uint4*)&dstw[4 * (size_t)g];
        s0 = sv.x; s1 = sv.z; d0 = dv.x; d1 = dv.z;
    }
    const float4* src = (const float4*)g_hw;
    float4 v0 = src[s0 * 16 + sub];
    asm volatile("red.global.add.v4.f32 [%0], {%1,%2,%3,%4};"
                 :: "l"(&g_agg[d0 * OUT_F + sub * 4]),
                    "f"(v0.x), "f"(v0.y), "f"(v0.z), "f"(v0.w) : "memory");
    float4 v1 = src[s1 * 16 + sub];
    asm volatile("red.global.add.v4.f32 [%0], {%1,%2,%3,%4};"
                 :: "l"(&g_agg[d1 * OUT_F + sub * 4]),
                    "f"(v1.x), "f"(v1.y), "f"(v1.z), "f"(v1.w) : "memory");
}

// ---------------- threefry2x32 (JAX-exact, 20 rounds) ----------------
__device__ __forceinline__ void threefry2x32(uint32_t k0, uint32_t k1,
                                             uint32_t x0, uint32_t x1,
                                             uint32_t& o0, uint32_t& o1) {
    uint32_t ks0 = k0, ks1 = k1, ks2 = 0x1BD11BDAu ^ k0 ^ k1;
    x0 += ks0; x1 += ks1;
#define TF_R(rr) { x0 += x1; x1 = (x1 << (rr)) | (x1 >> (32 - (rr))); x1 ^= x0; }
    TF_R(13) TF_R(15) TF_R(26) TF_R(6)  x0 += ks1; x1 += ks2 + 1u;
    TF_R(17) TF_R(29) TF_R(16) TF_R(24) x0 += ks2; x1 += ks0 + 2u;
    TF_R(13) TF_R(15) TF_R(26) TF_R(6)  x0 += ks0; x1 += ks1 + 3u;
    TF_R(17) TF_R(29) TF_R(16) TF_R(24) x0 += ks1; x1 += ks2 + 4u;
    TF_R(13) TF_R(15) TF_R(26) TF_R(6)  x0 += ks2; x1 += ks0 + 5u;
#undef TF_R
    o0 = x0; o1 = x1;
}

// ---------------- launch 3: relu + dropout mask + bf16 hi/lo split ----------------
__global__ __launch_bounds__(256) void k3_mask(const float* __restrict__ bias) {
    int i = blockIdx.x * 256 + threadIdx.x;
    uint32_t o0, o1;
    threefry2x32(0u, 42u, 0u, (uint32_t)i, o0, o1);
    uint32_t bits = o0 ^ o1;
    float u = __uint_as_float((bits >> 9) | 0x3f800000u) - 1.0f;
    float v = g_agg[i] + bias[i & 63];
    v = fmaxf(v, 0.0f);
    float y = (u < 0.7f) ? (v / 0.7f) : 0.0f;
    __nv_bfloat16 hi = __float2bfloat16(y);
    g_xhi[i] = hi;
    g_xlo[i] = __float2bfloat16(y - __bfloat162float(hi));
}

// ---------------- launch 4: out = x @ x^T, triangular 128x64 tiles, 4 CTA/SM ----------
// Tile (ti,cj), cj >= 2*ti: rows [ti*128,+128) x cols [cj*64,+64). Writes direct tile
// and its transpose (async bulk S2G). Diagonal-straddling tiles double-write consistent
// values (<=1 ulp). 256 threads, 4x2 warp grid, 48KB smem -> 4 CTAs/SM.
#define SM_AHI  0
#define SM_ALO  16384
#define SM_BHI  32768
#define SM_BLO  40960
#define SM_TOTAL 49152
#define STG_D 72    // direct stage stride (floats): 128 x 72 x 4 = 36864 B
#define STG_T 136   // transposed stage stride:       64 x 136 x 4 = 34816 B

__device__ __forceinline__ void ldsm_x4(uint32_t* r, uint32_t addr) {
    asm volatile("ldmatrix.sync.aligned.m8n8.x4.shared.b16 {%0,%1,%2,%3}, [%4];"
                 : "=r"(r[0]), "=r"(r[1]), "=r"(r[2]), "=r"(r[3]) : "r"(addr));
}
__device__ __forceinline__ void mma16816(float* d, const uint32_t* a,
                                         uint32_t b0, uint32_t b1) {
    asm volatile(
        "mma.sync.aligned.m16n8k16.row.col.f32.bf16.bf16.f32 "
        "{%0,%1,%2,%3}, {%4,%5,%6,%7}, {%8,%9}, {%0,%1,%2,%3};"
        : "+f"(d[0]), "+f"(d[1]), "+f"(d[2]), "+f"(d[3])
        : "r"(a[0]), "r"(a[1]), "r"(a[2]), "r"(a[3]), "r"(b0), "r"(b1));
}
__device__ __forceinline__ void cp_async16(uint32_t saddr, const void* gptr) {
    asm volatile("cp.async.cg.shared.global [%0], [%1], 16;"
                 :: "r"(saddr), "l"(gptr) : "memory");
}
__device__ __forceinline__ void bulk_store(void* gptr, uint32_t saddr, unsigned bytes) {
    asm volatile("cp.async.bulk.global.shared::cta.bulk_group [%0], [%1], %2;"
                 :: "l"(gptr), "r"(saddr), "r"(bytes) : "memory");
}

__global__ __launch_bounds__(256, 4)
void k4_gemm(float* __restrict__ out) {
    extern __shared__ char smem[];
    uint32_t sb = (uint32_t)__cvta_generic_to_shared(smem);
    int tid = threadIdx.x, wid = tid >> 5, lid = tid & 31;
    int wm = wid & 3, wn = wid >> 2;   // 4x2 warp grid; warp tile 32 rows x 32 cols

    // decode bid -> (ti, cj), cj >= 2*ti ; off(t) = t*(257 - t)
    int bid = blockIdx.x;
    int ti = (int)((257.0 - sqrt(257.0 * 257.0 - 4.0 * (double)bid)) * 0.5);
    if (ti < 0) ti = 0;
    while ((ti + 1) * (257 - (ti + 1)) <= bid) ti++;
    while (ti * (257 - ti) > bid) ti--;
    int cj = 2 * ti + (bid - ti * (257 - ti));
    int rowA = ti << 7;   // 128 rows
    int colB = cj << 6;   // 64 cols

    // ---- prologue: cp.async operand tiles with SW128 swizzle ----
    {
        const char* pAh = (const char*)(g_xhi + (size_t)rowA * OUT_F);
        const char* pAl = (const char*)(g_xlo + (size_t)rowA * OUT_F);
        const char* pBh = (const char*)(g_xhi + (size_t)colB * OUT_F);
        const char* pBl = (const char*)(g_xlo + (size_t)colB * OUT_F);
        #pragma unroll
        for (int j = 0; j < 4; j++) {
            int idx = tid + j * 256;                 // A: 1024 chunks each
            uint32_t bo = (uint32_t)(idx << 4);
            uint32_t sw = bo ^ ((bo >> 3) & 0x70);
            cp_async16(sb + SM_AHI + sw, pAh + ((size_t)idx << 4));
            cp_async16(sb + SM_ALO + sw, pAl + ((size_t)idx << 4));
        }
        #pragma unroll
        for (int j = 0; j < 2; j++) {
            int idx = tid + j * 256;                 // B: 512 chunks each
            uint32_t bo = (uint32_t)(idx << 4);
            uint32_t sw = bo ^ ((bo >> 3) & 0x70);
            cp_async16(sb + SM_BHI + sw, pBh + ((size_t)idx << 4));
            cp_async16(sb + SM_BLO + sw, pBl + ((size_t)idx << 4));
        }
        asm volatile("cp.async.commit_group;" ::: "memory");
        asm volatile("cp.async.wait_group 0;" ::: "memory");
    }
    __syncthreads();

    float acc[2][4][4];
    #pragma unroll
    for (int mt = 0; mt < 2; mt++)
        #pragma unroll
        for (int nt = 0; nt < 4; nt++)
            #pragma unroll
            for (int e = 0; e < 4; e++) acc[mt][nt][e] = 0.f;

    int lrow = lid & 15, lchk = lid >> 4, lswz = lid & 7;

    #pragma unroll
    for (int kc = 0; kc < 4; kc++) {
        uint32_t chunk = (uint32_t)(((2 * kc + lchk) ^ lswz) << 4);
        uint32_t ah[2][4], al[2][4];
        #pragma unroll
        for (int mt = 0; mt < 2; mt++) {
            uint32_t ro = (uint32_t)((wm * 32 + mt * 16 + lrow) * 128) + chunk;
            ldsm_x4(ah[mt], sb + SM_AHI + ro);
            ldsm_x4(al[mt], sb + SM_ALO + ro);
        }
        #pragma unroll
        for (int np = 0; np < 2; np++) {
            uint32_t bh[4], bl[4];
            uint32_t ro = (uint32_t)((wn * 32 + np * 16 + lrow) * 128) + chunk;
            ldsm_x4(bh, sb + SM_BHI + ro);
            ldsm_x4(bl, sb + SM_BLO + ro);
            #pragma unroll
            for (int mt = 0; mt < 2; mt++)
                #pragma unroll
                for (int sel = 0; sel < 2; sel++) {
                    int nt = np * 2 + sel;
                    mma16816(acc[mt][nt], ah[mt], bh[sel], bh[sel + 2]); // hi*hi
                    mma16816(acc[mt][nt], ah[mt], bl[sel], bl[sel + 2]); // hi*lo
                    mma16816(acc[mt][nt], al[mt], bh[sel], bh[sel + 2]); // lo*hi
                }
        }
    }
    __syncthreads();   // operands dead; reuse smem as stage

    float* stage = (float*)smem;
    int gid = lid >> 2, tig = lid & 3;

    // ---- pass 1: direct tile (128 x 64) -> stage(STG_D) -> bulk rows of 256 B ----
    #pragma unroll
    for (int mt = 0; mt < 2; mt++)
        #pragma unroll
        for (int half = 0; half < 2; half++) {
            int r = wm * 32 + mt * 16 + gid + 8 * half;
            #pragma unroll
            for (int nt = 0; nt < 4; nt++) {
                int c = wn * 32 + nt * 8 + tig * 2;
                *(float2*)&stage[r * STG_D + c] =
                    make_float2(acc[mt][nt][half * 2], acc[mt][nt][half * 2 + 1]);
            }
        }
    __syncthreads();
    if (tid < 128) {
        asm volatile("fence.proxy.async.shared::cta;" ::: "memory");
        bulk_store(out + (size_t)(rowA + tid) * 16384 + colB,
                   sb + (uint32_t)(tid * STG_D * 4), 256u);
        asm volatile("cp.async.bulk.commit_group;" ::: "memory");
    }

    // ---- pass 2: transposed tile (64 x 128) -> stage(STG_T) -> bulk rows of 512 B ----
    asm volatile("cp.async.bulk.wait_group 0;" ::: "memory");   // stage reusable
    __syncthreads();
    #pragma unroll
    for (int mt = 0; mt < 2; mt++)
        #pragma unroll
        for (int half = 0; half < 2; half++) {
            int r = wm * 32 + mt * 16 + gid + 8 * half;
            #pragma unroll
            for (int nt = 0; nt < 4; nt++) {
                int c = wn * 32 + nt * 8 + tig * 2;
                stage[c * STG_T + r]       = acc[mt][nt][half * 2];
                stage[(c + 1) * STG_T + r] = acc[mt][nt][half * 2 + 1];
            }
        }
    __syncthreads();
    if (tid < 64) {
        asm volatile("fence.proxy.async.shared::cta;" ::: "memory");
        bulk_store(out + (size_t)(colB + tid) * 16384 + rowA,
                   sb + (uint32_t)(tid * STG_T * 4), 512u);
        asm volatile("cp.async.bulk.commit_group;" ::: "memory");
        asm volatile("cp.async.bulk.wait_group 0;" ::: "memory");
    }
}

// ---------------- launch ----------------
extern "C" void kernel_launch(void* const* d_in, const int* in_sizes, int n_in,
                              void* d_out, int out_size) {
    const float*        h    = (const float*)d_in[0];
    const unsigned int* srcw = (const unsigned int*)d_in[1];
    const unsigned int* dstw = (const unsigned int*)d_in[2];
    const float*        W    = (const float*)d_in[3];
    const float*        bias = (const float*)d_in[4];
    float*              out  = (float*)d_out;

    k_fused1<<<6145, 256>>>(h, W, srcw);                    // 1
    k2_scatter<<<(NE / 2 * 16) / 256, 256>>>(srcw, dstw);   // 2
    k3_mask<<<(N_NODES * OUT_F) / 256, 256>>>(bias);        // 3

    cudaFuncSetAttribute(k4_gemm, cudaFuncAttributeMaxDynamicSharedMemorySize, SM_TOTAL);
    k4_gemm<<<N_TILES, 256, SM_TOTAL>>>(out);               // 4 (ncu target)
}

// round 13
// speedup vs baseline: 1.4841x; 1.0021x over previous
#include <cuda_runtime.h>
#include <cuda_bf16.h>
#include <stdint.h>

// ---------------- problem constants ----------------
#define N_NODES 16384
#define NE      524288
#define IN_F    128
#define OUT_F   64
#define N_TILES 16512   // sum over ti of (256 - 2*ti)

// ---------------- device scratch ----------------
__device__ float         g_hw [N_NODES * OUT_F];   // 4 MB
__device__ float         g_agg[N_NODES * OUT_F];   // 4 MB
__device__ __nv_bfloat16 g_xhi[N_NODES * OUT_F];   // 2 MB
__device__ __nv_bfloat16 g_xlo[N_NODES * OUT_F];   // 2 MB
__device__ int           g_is64;

// ---------------- launch 1: fused proj + zero(agg) + detect ----------------
__global__ __launch_bounds__(256) void k_fused1(const float* __restrict__ h,
                                                const float* __restrict__ W,
                                                const unsigned int* __restrict__ srcw) {
    int bid = blockIdx.x;
    int tid = threadIdx.x;
    if (bid < 2048) {
        __shared__ float sW[IN_F * OUT_F];
        __shared__ float sH[8][IN_F];
        int wid = tid >> 5, lid = tid & 31;
        for (int i = tid; i < IN_F * OUT_F; i += 256) sW[i] = W[i];
        int r = bid * 8 + wid;
        #pragma unroll
        for (int t = 0; t < 4; t++) sH[wid][lid + 32 * t] = h[(size_t)r * IN_F + lid + 32 * t];
        __syncthreads();
        float a0 = 0.f, a1 = 0.f;
        #pragma unroll
        for (int k = 0; k < IN_F; k++) {
            float hv = sH[wid][k];
            a0 += hv * sW[k * OUT_F + lid];
            a1 += hv * sW[k * OUT_F + lid + 32];
        }
        g_hw[r * OUT_F + lid]      = a0;
        g_hw[r * OUT_F + lid + 32] = a1;
    } else if (bid < 6144) {
        int i = (bid - 2048) * 256 + tid;
        g_agg[i] = 0.f;
    } else {
        __shared__ int cnt;
        if (tid == 0) cnt = 0;
        __syncthreads();
        int z = 0;
        for (int i = tid; i < 1024; i += 256)
            z += (srcw[2 * i + 1] == 0u) ? 1 : 0;
        atomicAdd(&cnt, z);
        __syncthreads();
        if (tid == 0) g_is64 = (cnt > 512) ? 1 : 0;
    }
}

// ---------------- launch 2: scatter, 2 edges per 16-lane group ----------------
__global__ __launch_bounds__(256) void k2_scatter(const unsigned int* __restrict__ srcw,
                                                  const unsigned int* __restrict__ dstw) {
    unsigned g = (blockIdx.x * 256u + threadIdx.x) >> 4;
    int sub = threadIdx.x & 15;
    unsigned s0, s1, d0, d1;
    if (!g_is64) {
        uint2 sv = *(const uint2*)&srcw[2 * (size_t)g];
        uint2 dv = *(const uint2*)&dstw[2 * (size_t)g];
        s0 = sv.x; s1 = sv.y; d0 = dv.x; d1 = dv.y;
    } else {
        uint4 sv = *(const uint4*)&srcw[4 * (size_t)g];
        uint4 dv = *(const uint4*)&dstw[4 * (size_t)g];
        s0 = sv.x; s1 = sv.z; d0 = dv.x; d1 = dv.z;
    }
    const float4* src = (const float4*)g_hw;
    float4 v0 = src[s0 * 16 + sub];
    asm volatile("red.global.add.v4.f32 [%0], {%1,%2,%3,%4};"
                 :: "l"(&g_agg[d0 * OUT_F + sub * 4]),
                    "f"(v0.x), "f"(v0.y), "f"(v0.z), "f"(v0.w) : "memory");
    float4 v1 = src[s1 * 16 + sub];
    asm volatile("red.global.add.v4.f32 [%0], {%1,%2,%3,%4};"
                 :: "l"(&g_agg[d1 * OUT_F + sub * 4]),
                    "f"(v1.x), "f"(v1.y), "f"(v1.z), "f"(v1.w) : "memory");
}

// ---------------- threefry2x32 (JAX-exact, 20 rounds) ----------------
__device__ __forceinline__ void threefry2x32(uint32_t k0, uint32_t k1,
                                             uint32_t x0, uint32_t x1,
                                             uint32_t& o0, uint32_t& o1) {
    uint32_t ks0 = k0, ks1 = k1, ks2 = 0x1BD11BDAu ^ k0 ^ k1;
    x0 += ks0; x1 += ks1;
#define TF_R(rr) { x0 += x1; x1 = (x1 << (rr)) | (x1 >> (32 - (rr))); x1 ^= x0; }
    TF_R(13) TF_R(15) TF_R(26) TF_R(6)  x0 += ks1; x1 += ks2 + 1u;
    TF_R(17) TF_R(29) TF_R(16) TF_R(24) x0 += ks2; x1 += ks0 + 2u;
    TF_R(13) TF_R(15) TF_R(26) TF_R(6)  x0 += ks0; x1 += ks1 + 3u;
    TF_R(17) TF_R(29) TF_R(16) TF_R(24) x0 += ks1; x1 += ks2 + 4u;
    TF_R(13) TF_R(15) TF_R(26) TF_R(6)  x0 += ks2; x1 += ks0 + 5u;
#undef TF_R
    o0 = x0; o1 = x1;
}

// ---------------- launch 3: relu + dropout mask + bf16 hi/lo split ----------------
__global__ __launch_bounds__(256) void k3_mask(const float* __restrict__ bias) {
    int i = blockIdx.x * 256 + threadIdx.x;
    uint32_t o0, o1;
    threefry2x32(0u, 42u, 0u, (uint32_t)i, o0, o1);
    uint32_t bits = o0 ^ o1;
    float u = __uint_as_float((bits >> 9) | 0x3f800000u) - 1.0f;
    float v = g_agg[i] + bias[i & 63];
    v = fmaxf(v, 0.0f);
    float y = (u < 0.7f) ? (v / 0.7f) : 0.0f;
    __nv_bfloat16 hi = __float2bfloat16(y);
    g_xhi[i] = hi;
    g_xlo[i] = __float2bfloat16(y - __bfloat162float(hi));
}

// ---------------- launch 4: out = x @ x^T, triangular 128x64 tiles, 4 CTA/SM ----------
// Tile (ti,cj), cj >= 2*ti: rows [ti*128,+128) x cols [cj*64,+64). Writes direct tile
// and its transpose (async bulk S2G). Diagonal-straddling tiles double-write consistent
// values (<=1 ulp). 256 threads, 4x2 warp grid, 48KB smem -> 4 CTAs/SM.
#define SM_AHI  0
#define SM_ALO  16384
#define SM_BHI  32768
#define SM_BLO  40960
#define SM_TOTAL 49152
#define STG_D 72    // direct stage stride (floats): 128 x 72 x 4 = 36864 B
#define STG_T 136   // transposed stage stride:       64 x 136 x 4 = 34816 B

__device__ __forceinline__ void ldsm_x4(uint32_t* r, uint32_t addr) {
    asm volatile("ldmatrix.sync.aligned.m8n8.x4.shared.b16 {%0,%1,%2,%3}, [%4];"
                 : "=r"(r[0]), "=r"(r[1]), "=r"(r[2]), "=r"(r[3]) : "r"(addr));
}
__device__ __forceinline__ void mma16816(float* d, const uint32_t* a,
                                         uint32_t b0, uint32_t b1) {
    asm volatile(
        "mma.sync.aligned.m16n8k16.row.col.f32.bf16.bf16.f32 "
        "{%0,%1,%2,%3}, {%4,%5,%6,%7}, {%8,%9}, {%0,%1,%2,%3};"
        : "+f"(d[0]), "+f"(d[1]), "+f"(d[2]), "+f"(d[3])
        : "r"(a[0]), "r"(a[1]), "r"(a[2]), "r"(a[3]), "r"(b0), "r"(b1));
}
__device__ __forceinline__ void cp_async16(uint32_t saddr, const void* gptr) {
    asm volatile("cp.async.cg.shared.global [%0], [%1], 16;"
                 :: "r"(saddr), "l"(gptr) : "memory");
}
__device__ __forceinline__ void bulk_store(void* gptr, uint32_t saddr, unsigned bytes) {
    asm volatile("cp.async.bulk.global.shared::cta.bulk_group [%0], [%1], %2;"
                 :: "l"(gptr), "r"(saddr), "r"(bytes) : "memory");
}

__global__ __launch_bounds__(256, 4)
void k4_gemm(float* __restrict__ out) {
    extern __shared__ char smem[];
    uint32_t sb = (uint32_t)__cvta_generic_to_shared(smem);
    int tid = threadIdx.x, wid = tid >> 5, lid = tid & 31;
    int wm = wid & 3, wn = wid >> 2;   // 4x2 warp grid; warp tile 32 rows x 32 cols

    // decode bid -> (ti, cj), cj >= 2*ti ; off(t) = t*(257 - t)
    int bid = blockIdx.x;
    int ti = (int)((257.0 - sqrt(257.0 * 257.0 - 4.0 * (double)bid)) * 0.5);
    if (ti < 0) ti = 0;
    while ((ti + 1) * (257 - (ti + 1)) <= bid) ti++;
    while (ti * (257 - ti) > bid) ti--;
    int cj = 2 * ti + (bid - ti * (257 - ti));
    int rowA = ti << 7;   // 128 rows
    int colB = cj << 6;   // 64 cols

    // ---- prologue: cp.async operand tiles with SW128 swizzle ----
    {
        const char* pAh = (const char*)(g_xhi + (size_t)rowA * OUT_F);
        const char* pAl = (const char*)(g_xlo + (size_t)rowA * OUT_F);
        const char* pBh = (const char*)(g_xhi + (size_t)colB * OUT_F);
        const char* pBl = (const char*)(g_xlo + (size_t)colB * OUT_F);
        #pragma unroll
        for (int j = 0; j < 4; j++) {
            int idx = tid + j * 256;                 // A: 1024 chunks each
            uint32_t bo = (uint32_t)(idx << 4);
            uint32_t sw = bo ^ ((bo >> 3) & 0x70);
            cp_async16(sb + SM_AHI + sw, pAh + ((size_t)idx << 4));
            cp_async16(sb + SM_ALO + sw, pAl + ((size_t)idx << 4));
        }
        #pragma unroll
        for (int j = 0; j < 2; j++) {
            int idx = tid + j * 256;                 // B: 512 chunks each
            uint32_t bo = (uint32_t)(idx << 4);
            uint32_t sw = bo ^ ((bo >> 3) & 0x70);
            cp_async16(sb + SM_BHI + sw, pBh + ((size_t)idx << 4));
            cp_async16(sb + SM_BLO + sw, pBl + ((size_t)idx << 4));
        }
        asm volatile("cp.async.commit_group;" ::: "memory");
        asm volatile("cp.async.wait_group 0;" ::: "memory");
    }
    __syncthreads();

    float acc[2][4][4];
    #pragma unroll
    for (int mt = 0; mt < 2; mt++)
        #pragma unroll
        for (int nt = 0; nt < 4; nt++)
            #pragma unroll
            for (int e = 0; e < 4; e++) acc[mt][nt][e] = 0.f;

    int lrow = lid & 15, lchk = lid >> 4, lswz = lid & 7;

    #pragma unroll
    for (int kc = 0; kc < 4; kc++) {
        uint32_t chunk = (uint32_t)(((2 * kc + lchk) ^ lswz) << 4);
        uint32_t ah[2][4], al[2][4];
        #pragma unroll
        for (int mt = 0; mt < 2; mt++) {
            uint32_t ro = (uint32_t)((wm * 32 + mt * 16 + lrow) * 128) + chunk;
            ldsm_x4(ah[mt], sb + SM_AHI + ro);
            ldsm_x4(al[mt], sb + SM_ALO + ro);
        }
        #pragma unroll
        for (int np = 0; np < 2; np++) {
            uint32_t bh[4], bl[4];
            uint32_t ro = (uint32_t)((wn * 32 + np * 16 + lrow) * 128) + chunk;
            ldsm_x4(bh, sb + SM_BHI + ro);
            ldsm_x4(bl, sb + SM_BLO + ro);
            #pragma unroll
            for (int mt = 0; mt < 2; mt++)
                #pragma unroll
                for (int sel = 0; sel < 2; sel++) {
                    int nt = np * 2 + sel;
                    mma16816(acc[mt][nt], ah[mt], bh[sel], bh[sel + 2]); // hi*hi
                    mma16816(acc[mt][nt], ah[mt], bl[sel], bl[sel + 2]); // hi*lo
                    mma16816(acc[mt][nt], al[mt], bh[sel], bh[sel + 2]); // lo*hi
                }
        }
    }
    __syncthreads();   // operands dead; reuse smem as stage

    float* stage = (float*)smem;
    int gid = lid >> 2, tig = lid & 3;

    // ---- pass 1: direct tile (128 x 64) -> stage(STG_D) -> bulk rows of 256 B ----
    #pragma unroll
    for (int mt = 0; mt < 2; mt++)
        #pragma unroll
        for (int half = 0; half < 2; half++) {
            int r = wm * 32 + mt * 16 + gid + 8 * half;
            #pragma unroll
            for (int nt = 0; nt < 4; nt++) {
                int c = wn * 32 + nt * 8 + tig * 2;
                *(float2*)&stage[r * STG_D + c] =
                    make_float2(acc[mt][nt][half * 2], acc[mt][nt][half * 2 + 1]);
            }
        }
    __syncthreads();
    if (tid < 128) {
        asm volatile("fence.proxy.async.shared::cta;" ::: "memory");
        bulk_store(out + (size_t)(rowA + tid) * 16384 + colB,
                   sb + (uint32_t)(tid * STG_D * 4), 256u);
        asm volatile("cp.async.bulk.commit_group;" ::: "memory");
    }

    // ---- pass 2: transposed tile (64 x 128) -> stage(STG_T) -> bulk rows of 512 B ----
    asm volatile("cp.async.bulk.wait_group 0;" ::: "memory");   // stage reusable
    __syncthreads();
    #pragma unroll
    for (int mt = 0; mt < 2; mt++)
        #pragma unroll
        for (int half = 0; half < 2; half++) {
            int r = wm * 32 + mt * 16 + gid + 8 * half;
            #pragma unroll
            for (int nt = 0; nt < 4; nt++) {
                int c = wn * 32 + nt * 8 + tig * 2;
                stage[c * STG_T + r]       = acc[mt][nt][half * 2];
                stage[(c + 1) * STG_T + r] = acc[mt][nt][half * 2 + 1];
            }
        }
    __syncthreads();
    if (tid < 64) {
        asm volatile("fence.proxy.async.shared::cta;" ::: "memory");
        bulk_store(out + (size_t)(colB + tid) * 16384 + rowA,
                   sb + (uint32_t)(tid * STG_T * 4), 512u);
        asm volatile("cp.async.bulk.commit_group;" ::: "memory");
        asm volatile("cp.async.bulk.wait_group 0;" ::: "memory");
    }
}

// ---------------- launch ----------------
extern "C" void kernel_launch(void* const* d_in, const int* in_sizes, int n_in,
                              void* d_out, int out_size) {
    const float*        h    = (const float*)d_in[0];
    const unsigned int* srcw = (const unsigned int*)d_in[1];
    const unsigned int* dstw = (const unsigned int*)d_in[2];
    const float*        W    = (const float*)d_in[3];
    const float*        bias = (const float*)d_in[4];
    float*              out  = (float*)d_out;

    k_fused1<<<6145, 256>>>(h, W, srcw);                    // 1
    k2_scatter<<<(NE / 2 * 16) / 256, 256>>>(srcw, dstw);   // 2
    k3_mask<<<(N_NODES * OUT_F) / 256, 256>>>(bias);        // 3

    cudaFuncSetAttribute(k4_gemm, cudaFuncAttributeMaxDynamicSharedMemorySize, SM_TOTAL);
    k4_gemm<<<N_TILES, 256, SM_TOTAL>>>(out);               // 4 (ncu target)
}